// round 15
// baseline (speedup 1.0000x reference)
#include <cuda_runtime.h>
#include <cuda_fp16.h>
#include <cstdint>
#include <cstddef>

#define TPB   128
#define NKEY  127
#define NH    4
#define DK    64
#define DOUT  256
#define STRH  80    // fp16 kv/wk row stride in halves (160B)
#define STRW  136   // fp16 w row stride in halves
#define STGF  68    // fp32 staging row stride in floats
#define MAXT  4

static constexpr int OFFB_STG  = 0;
static constexpr int OFFB_KV16 = OFFB_STG  + 128 * STGF * 4;
static constexpr int OFFB_WK16 = OFFB_KV16 + 128 * STRH * 2;
static constexpr int OFFB_QBA  = OFFB_WK16 + 256 * STRH * 2;
static constexpr int OFFB_QT   = OFFB_QBA + MAXT * DOUT * 4;
static constexpr int OFFB_WS   = OFFB_QT + MAXT * DK * 4;
static constexpr int OFFB_W16  = OFFB_WS + DK * 4;             // [16][STRW] fp16
static constexpr int OFFB_WV   = OFFB_W16 + 16 * STRW * 2;     // [256] f32
static constexpr int OFFB_BS   = OFFB_WV + DOUT * 4;
static constexpr int SMEM_BYTES = OFFB_BS + 16;                // ~107 KB

__device__ __forceinline__ uint32_t f2h2(float a, float b) {
    __half2 h = __floats2half2_rn(a, b);
    return *(uint32_t*)&h;
}
__device__ __forceinline__ uint32_t tanh_h2(uint32_t x) {
    uint32_t y;
    asm("tanh.approx.f16x2 %0, %1;" : "=r"(y) : "r"(x));
    return y;
}

// m16n8k16 fp16 MMA, row(A) x col(B), fp32 accumulate (arch-neutral PTX)
__device__ __forceinline__ void mma16(float& d0, float& d1, float& d2,
                                      float& d3, uint32_t a0, uint32_t a1,
                                      uint32_t a2, uint32_t a3,
                                      uint32_t b0, uint32_t b1) {
    asm volatile(
        "mma.sync.aligned.m16n8k16.row.col.f32.f16.f16.f32 "
        "{%0,%1,%2,%3}, {%4,%5,%6,%7}, {%8,%9}, {%0,%1,%2,%3};"
        : "+f"(d0), "+f"(d1), "+f"(d2), "+f"(d3)
        : "r"(a0), "r"(a1), "r"(a2), "r"(a3), "r"(b0), "r"(b1));
}

// ldmatrix x2 transposed b16: B fragment from row-major [K,N] memory
__device__ __forceinline__ void ldmx2t(uint32_t& r0, uint32_t& r1,
                                       uint32_t saddr) {
    asm volatile(
        "ldmatrix.sync.aligned.m8n8.x2.trans.shared.b16 {%0,%1}, [%2];"
        : "=r"(r0), "=r"(r1) : "r"(saddr));
}

#define CP_ASYNC16(sdst, gsrc)                                                \
    asm volatile("cp.async.cg.shared.global [%0], [%1], 16;"                  \
                 :: "r"(sdst), "l"(gsrc))
#define CP_COMMIT() asm volatile("cp.async.commit_group;")
#define CP_WAIT0()  asm volatile("cp.async.wait_group 0;")

__device__ __forceinline__ void prefetch_kv(const float* __restrict__ gsrc,
                                            float* stg) {
    #pragma unroll 1
    for (int j = threadIdx.x; j < NKEY * 16; j += TPB) {
        int row = j >> 4;
        int c4  = j & 15;
        unsigned sa =
            (unsigned)__cvta_generic_to_shared(stg + row * STGF + c4 * 4);
        CP_ASYNC16(sa, gsrc + j * 4);
    }
}

__device__ __forceinline__ void convert_kv(const float* s_stg,
                                           __half* s_kvh, int tid) {
    if (tid < NKEY) {
        const float* src = s_stg + tid * STGF;
        __half* dst = s_kvh + tid * STRH;
        #pragma unroll
        for (int u = 0; u < 16; ++u) {
            float4 v = *(const float4*)(src + u * 4);
            uint2 hh = make_uint2(f2h2(v.x, v.y), f2h2(v.z, v.w));
            *(uint2*)(dst + u * 4) = hh;
        }
    }
}

__global__ void __launch_bounds__(TPB, 2)
raamh_kernel(const float* __restrict__ q_x, const float* __restrict__ kv_x,
             const float* __restrict__ Wk,  const float* __restrict__ Wq,
             const float* __restrict__ Wv,  const float* __restrict__ bias,
             const float* __restrict__ Ws,  const float* __restrict__ bs,
             float* __restrict__ out, int BT)
{
    extern __shared__ char smem[];
    float*  s_stg  = (float*) (smem + OFFB_STG);
    __half* s_kvh  = (__half*)(smem + OFFB_KV16);
    __half* s_wkh  = (__half*)(smem + OFFB_WK16);
    float*  s_qba  = (float*) (smem + OFFB_QBA);
    float*  s_qt   = (float*) (smem + OFFB_QT);
    float*  s_ws   = (float*) (smem + OFFB_WS);
    __half* s_w16  = (__half*)(smem + OFFB_W16);   // [16][STRW]
    float*  s_wv   = (float*) (smem + OFFB_WV);
    float*  s_bs   = (float*) (smem + OFFB_BS);

    const int tid  = threadIdx.x;
    const int lane = tid & 31;
    const int wrp  = tid >> 5;       // warp's head
    const int g    = lane >> 2;
    const int tg   = lane & 3;

    const int bt0  = blockIdx.x;
    const int grid = gridDim.x;
    int ntiles = (BT - bt0 + grid - 1) / grid;
    if (ntiles > MAXT) ntiles = MAXT;
    if (ntiles < 1) return;

    prefetch_kv(kv_x + (size_t)bt0 * (NKEY * DK), s_stg);
    CP_COMMIT();

    // ---- one-time staging ----
    {
        #pragma unroll 1
        for (int j = tid; j < DOUT * 16; j += TPB) {
            int row = j >> 4, c4 = (j & 15) * 4;
            float4 v = __ldg((const float4*)(Wk + row * DK + c4));
            uint2 hh = make_uint2(f2h2(v.x, v.y), f2h2(v.z, v.w));
            *(uint2*)(s_wkh + row * STRH + c4) = hh;
        }
        if (tid < DK) s_ws[tid] = Ws[tid];
        if (tid == 0) s_bs[0] = bs[0];
        if (tid < 16) {   // zero kv row 127 once
            uint2 z = make_uint2(0u, 0u);
            *(uint2*)(s_kvh + 127 * STRH + tid * 4) = z;
        }
        for (int j = tid; j < 16 * STRW / 2; j += TPB)   // zero s_w16
            ((uint32_t*)s_w16)[j] = 0u;
        for (int idx = tid; idx < ntiles * DK; idx += TPB) {
            int t = idx >> 6, k = idx & 63;
            s_qt[t * DK + k] = q_x[(size_t)(bt0 + t * grid) * DK + k];
        }
    }
    __syncthreads();

    // ---- prologue: qb for every tile; thread covers o = tid, tid+128 ----
    #pragma unroll 1
    for (int rep = 0; rep < 2; ++rep) {
        const int o = tid + rep * 128;
        float4 wq[16];
        const float4* wq4 = (const float4*)(Wq + o * DK);
        #pragma unroll
        for (int i = 0; i < 16; i++) wq[i] = __ldg(wq4 + i);
        const float bb = __ldg(bias + (o & (DK - 1)));
        #pragma unroll 1
        for (int t = 0; t < ntiles; ++t) {
            const float* qq = s_qt + t * DK;
            float a0 = 0.f, a1 = 0.f, a2 = 0.f, a3 = 0.f;
            #pragma unroll
            for (int i = 0; i < 16; i++) {
                a0 = fmaf(qq[4 * i + 0], wq[i].x, a0);
                a1 = fmaf(qq[4 * i + 1], wq[i].y, a1);
                a2 = fmaf(qq[4 * i + 2], wq[i].z, a2);
                a3 = fmaf(qq[4 * i + 3], wq[i].w, a3);
            }
            s_qba[t * DOUT + o] = (a0 + a1) + (a2 + a3) + bb;
        }
    }

    // ---- first tile: wait + convert before main loop ----
    CP_WAIT0();
    __syncthreads();
    convert_kv(s_stg, s_kvh, tid);
    __syncthreads();
    if (bt0 + grid < BT) {
        prefetch_kv(kv_x + (size_t)(bt0 + grid) * (NKEY * DK), s_stg);
        CP_COMMIT();
    }

    int ti = 0;
    for (int bt = bt0; bt < BT; bt += grid, ++ti) {
        const float* qbt = s_qba + ti * DOUT;
        const float  bsv = s_bs[0];
        const int head = wrp;
        const __half* wkp = s_wkh + (head * 64) * STRH;

        // ---- score GEMM + f16x2-tanh epilogue; scores kept in regs ----
        float sc[16];              // i = nh*4 + mb*2 + p -> n = nh*32+mb*16+p*8+g
        #pragma unroll 1
        for (int nh = 0; nh < 4; ++nh) {
            const __half* kvp = s_kvh + (nh * 32) * STRH;

            float acc[2][8][4];
            #pragma unroll
            for (int mb = 0; mb < 2; ++mb)
                #pragma unroll
                for (int nb = 0; nb < 8; ++nb)
                    #pragma unroll
                    for (int c = 0; c < 4; ++c) acc[mb][nb][c] = 0.f;

            #pragma unroll
            for (int kc = 0; kc < 4; ++kc) {
                const int ho = kc * 16 + 4 * tg;   // permuted k slots
                uint2 u[2], v[2];
                #pragma unroll
                for (int mb = 0; mb < 2; ++mb) {
                    const __half* ar = kvp + (mb * 16 + g) * STRH + ho;
                    u[mb] = *(const uint2*)ar;
                    v[mb] = *(const uint2*)(ar + 8 * STRH);
                }
                #pragma unroll
                for (int nb = 0; nb < 8; ++nb) {
                    uint2 w = *(const uint2*)(wkp + (nb * 8 + g) * STRH + ho);
                    #pragma unroll
                    for (int mb = 0; mb < 2; ++mb)
                        mma16(acc[mb][nb][0], acc[mb][nb][1],
                              acc[mb][nb][2], acc[mb][nb][3],
                              u[mb].x, v[mb].x, u[mb].y, v[mb].y,
                              w.x, w.y);
                }
            }

            // epilogue: f16x2 tanh + Ws reduction over this head's 64 o
            float part[2][2];
            part[0][0] = part[0][1] = part[1][0] = part[1][1] = 0.f;
            #pragma unroll
            for (int nb = 0; nb < 8; ++nb) {
                #pragma unroll
                for (int cc = 0; cc < 2; ++cc) {
                    const int k = nb * 8 + tg * 2 + cc;
                    const float wsk = s_ws[k];
                    const float qbo = qbt[head * 64 + k];
                    #pragma unroll
                    for (int mb = 0; mb < 2; ++mb) {
                        uint32_t pk = f2h2(acc[mb][nb][cc] + qbo,
                                           acc[mb][nb][2 + cc] + qbo);
                        uint32_t th = tanh_h2(pk);
                        float2 tf = __half22float2(*(__half2*)&th);
                        part[mb][0] = fmaf(wsk, tf.x, part[mb][0]);
                        part[mb][1] = fmaf(wsk, tf.y, part[mb][1]);
                    }
                }
            }
            #pragma unroll
            for (int m = 1; m <= 2; m <<= 1) {
                #pragma unroll
                for (int mb = 0; mb < 2; ++mb) {
                    part[mb][0] += __shfl_xor_sync(0xffffffffu, part[mb][0], m);
                    part[mb][1] += __shfl_xor_sync(0xffffffffu, part[mb][1], m);
                }
            }
            sc[nh * 4 + 0] = part[0][0] + bsv;
            sc[nh * 4 + 1] = part[0][1] + bsv;
            sc[nh * 4 + 2] = part[1][0] + bsv;
            sc[nh * 4 + 3] = part[1][1] + bsv;
        }

        // mask n = 127 (i=15, g=7)
        if (g == 7) sc[15] = -1e30f;

        // ---- in-register softmax over 128 scores (values uniform in tg) ----
        float mx = -1e30f;
        #pragma unroll
        for (int i = 0; i < 16; ++i) mx = fmaxf(mx, sc[i]);
        #pragma unroll
        for (int off = 4; off <= 16; off <<= 1)
            mx = fmaxf(mx, __shfl_xor_sync(0xffffffffu, mx, off));
        float sum = 0.f;
        #pragma unroll
        for (int i = 0; i < 16; ++i) {
            sc[i] = __expf(sc[i] - mx);
            sum += sc[i];
        }
        #pragma unroll
        for (int off = 4; off <= 16; off <<= 1)
            sum += __shfl_xor_sync(0xffffffffu, sum, off);
        const float inv = 1.f / sum;
        if (tg == 0) {
            #pragma unroll
            for (int i = 0; i < 16; ++i) {
                const int n = (i >> 2) * 32 + ((i >> 1) & 1) * 16 +
                              (i & 1) * 8 + g;
                s_w16[head * STRW + n] = __float2half(sc[i] * inv);
            }
        }
        __syncthreads();           // all 4 w rows ready for PV MMA

        // ---- P·V via tensor cores: warp owns 16 cols ----
        {
            const int c0 = wrp * 16;
            float pv[2][4];
            #pragma unroll
            for (int cc = 0; cc < 2; ++cc)
                #pragma unroll
                for (int c = 0; c < 4; ++c) pv[cc][c] = 0.f;

            #pragma unroll
            for (int kc = 0; kc < 8; ++kc) {
                const int k0 = kc * 16;
                uint32_t a0 = *(const uint32_t*)(s_w16 + g * STRW + k0 + 2 * tg);
                uint32_t a1 = *(const uint32_t*)(s_w16 + (g + 8) * STRW + k0 + 2 * tg);
                uint32_t a2 = *(const uint32_t*)(s_w16 + g * STRW + k0 + 8 + 2 * tg);
                uint32_t a3 = *(const uint32_t*)(s_w16 + (g + 8) * STRW + k0 + 8 + 2 * tg);
                #pragma unroll
                for (int cc = 0; cc < 2; ++cc) {
                    uint32_t baddr = (uint32_t)__cvta_generic_to_shared(
                        s_kvh + (k0 + (lane & 15)) * STRH + c0 + cc * 8);
                    uint32_t b0, b1;
                    ldmx2t(b0, b1, baddr);
                    mma16(pv[cc][0], pv[cc][1], pv[cc][2], pv[cc][3],
                          a0, a1, a2, a3, b0, b1);
                }
            }
            if (g < NH) {
                #pragma unroll
                for (int cc = 0; cc < 2; ++cc) {
                    s_wv[g * 64 + c0 + cc * 8 + 2 * tg]     = pv[cc][0];
                    s_wv[g * 64 + c0 + cc * 8 + 2 * tg + 1] = pv[cc][1];
                }
            }
        }
        __syncthreads();           // wv ready; kv16 dead from here

        // ---- out-projection + hidden convert of NEXT tile ----
        const int bt_next = bt + grid;
        if (bt_next < BT) {
            CP_WAIT0();            // staging for bt_next arrived
            convert_kv(s_stg, s_kvh, tid);
        }
        #pragma unroll 1
        for (int rep = 0; rep < 2; ++rep) {
            const int o = tid + rep * 128;
            const float* wvh = s_wv + (o >> 6) * 64;
            const float4* wv4 = (const float4*)(Wv + o * DK);
            float a0 = 0.f, a1 = 0.f, a2 = 0.f, a3 = 0.f;
            #pragma unroll
            for (int i = 0; i < 16; i++) {
                float4 w = __ldg(wv4 + i);
                a0 = fmaf(wvh[4 * i + 0], w.x, a0);
                a1 = fmaf(wvh[4 * i + 1], w.y, a1);
                a2 = fmaf(wvh[4 * i + 2], w.z, a2);
                a3 = fmaf(wvh[4 * i + 3], w.w, a3);
            }
            out[(size_t)bt * DOUT + o] = (a0 + a1) + (a2 + a3);
        }
        __syncthreads();           // kv16(next) ready; staging free

        if (bt + 2 * grid < BT) {
            prefetch_kv(kv_x + (size_t)(bt + 2 * grid) * (NKEY * DK), s_stg);
            CP_COMMIT();
        }
    }
}

extern "C" void kernel_launch(void* const* d_in, const int* in_sizes, int n_in,
                              void* d_out, int out_size) {
    (void)n_in; (void)out_size;
    const float* q_x  = (const float*)d_in[0];
    const float* kv_x = (const float*)d_in[1];
    const float* Wk   = (const float*)d_in[2];
    const float* Wq   = (const float*)d_in[3];
    const float* Wv   = (const float*)d_in[4];
    const float* bias = (const float*)d_in[5];
    const float* Ws   = (const float*)d_in[6];
    const float* bs   = (const float*)d_in[7];
    float* out = (float*)d_out;

    const int BT = in_sizes[0] / DK;
    int grid = 2 * 152;
    if (grid > BT) grid = BT;
    while ((BT + grid - 1) / grid > MAXT) grid += 2 * 152;

    cudaFuncSetAttribute(raamh_kernel,
                         cudaFuncAttributeMaxDynamicSharedMemorySize,
                         SMEM_BYTES);
    raamh_kernel<<<grid, TPB, SMEM_BYTES>>>(q_x, kv_x, Wk, Wq, Wv,
                                            bias, Ws, bs, out, BT);
}

// round 16
// speedup vs baseline: 1.0731x; 1.0731x over previous
#include <cuda_runtime.h>
#include <cuda_fp16.h>
#include <cstdint>
#include <cstddef>

#define TPB   512
#define GTH   128   // threads per group
#define NKEY  127
#define NH    4
#define DK    64
#define DOUT  256
#define STRH  80    // fp16 kv/wk row stride in halves (160B)
#define STRW  136   // fp16 w row stride in halves
#define MAXT  8

// shared region
static constexpr int OFF_WK  = 0;                       // 256*80*2 = 40960
static constexpr int OFF_WS  = OFF_WK + 256 * STRH * 2; // 64 f
static constexpr int OFF_BS  = OFF_WS + DK * 4;
static constexpr int OFF_GRP = OFF_BS + 16;             // 41232
// per-group region
static constexpr int GOFF_KV  = 0;                      // 128*80*2 = 20480
static constexpr int GOFF_QBA = GOFF_KV + 128 * STRH * 2;   // MAXT*256*4 = 8192
static constexpr int GOFF_QT  = GOFF_QBA + MAXT * DOUT * 4; // MAXT*64*4 = 2048
static constexpr int GOFF_W16 = GOFF_QT + MAXT * DK * 4;    // 16*136*2 = 4352
static constexpr int GOFF_WV  = GOFF_W16 + 16 * STRW * 2;   // 256*4 = 1024
static constexpr int GRP_SZ   = GOFF_WV + DOUT * 4;         // 36096
static constexpr int SMEM_BYTES = OFF_GRP + 4 * GRP_SZ;     // 185616

__device__ __forceinline__ uint32_t f2h2(float a, float b) {
    __half2 h = __floats2half2_rn(a, b);
    return *(uint32_t*)&h;
}
__device__ __forceinline__ uint32_t tanh_h2(uint32_t x) {
    uint32_t y;
    asm("tanh.approx.f16x2 %0, %1;" : "=r"(y) : "r"(x));
    return y;
}
#define GBAR(id)                                                              \
    asm volatile("bar.sync %0, %1;" :: "r"(id), "r"(GTH) : "memory")

// m16n8k16 fp16 MMA, row(A) x col(B), fp32 accumulate (arch-neutral PTX)
__device__ __forceinline__ void mma16(float& d0, float& d1, float& d2,
                                      float& d3, uint32_t a0, uint32_t a1,
                                      uint32_t a2, uint32_t a3,
                                      uint32_t b0, uint32_t b1) {
    asm volatile(
        "mma.sync.aligned.m16n8k16.row.col.f32.f16.f16.f32 "
        "{%0,%1,%2,%3}, {%4,%5,%6,%7}, {%8,%9}, {%0,%1,%2,%3};"
        : "+f"(d0), "+f"(d1), "+f"(d2), "+f"(d3)
        : "r"(a0), "r"(a1), "r"(a2), "r"(a3), "r"(b0), "r"(b1));
}
__device__ __forceinline__ void ldmx2t(uint32_t& r0, uint32_t& r1,
                                       uint32_t saddr) {
    asm volatile(
        "ldmatrix.sync.aligned.m8n8.x2.trans.shared.b16 {%0,%1}, [%2];"
        : "=r"(r0), "=r"(r1) : "r"(saddr));
}

// direct gmem->fp16 smem convert of one kv tile (group-local, 128 threads)
__device__ __forceinline__ void convert_kv(const float* __restrict__ gsrc,
                                           __half* s_kvh, int wtid) {
    #pragma unroll 4
    for (int j = wtid; j < NKEY * 16; j += GTH) {
        int row = j >> 4, c4 = (j & 15) * 4;
        float4 v = __ldg((const float4*)(gsrc + j * 4));
        uint2 hh = make_uint2(f2h2(v.x, v.y), f2h2(v.z, v.w));
        *(uint2*)(s_kvh + row * STRH + c4) = hh;
    }
}

__global__ void __launch_bounds__(TPB)
raamh_kernel(const float* __restrict__ q_x, const float* __restrict__ kv_x,
             const float* __restrict__ Wk,  const float* __restrict__ Wq,
             const float* __restrict__ Wv,  const float* __restrict__ bias,
             const float* __restrict__ Ws,  const float* __restrict__ bs,
             float* __restrict__ out, int BT)
{
    extern __shared__ char smem[];
    __half* s_wkh = (__half*)(smem + OFF_WK);
    float*  s_ws  = (float*) (smem + OFF_WS);
    float*  s_bs  = (float*) (smem + OFF_BS);

    const int tid  = threadIdx.x;
    const int grp  = tid >> 7;       // group 0..3
    const int wtid = tid & 127;      // thread within group
    const int lane = tid & 31;
    const int wrp  = wtid >> 5;      // head within group
    const int g    = lane >> 2;
    const int tg   = lane & 3;

    char*   gb    = smem + OFF_GRP + grp * GRP_SZ;
    __half* s_kvh = (__half*)(gb + GOFF_KV);
    float*  s_qba = (float*) (gb + GOFF_QBA);
    float*  s_qt  = (float*) (gb + GOFF_QT);
    __half* s_w16 = (__half*)(gb + GOFF_W16);
    float*  s_wv  = (float*) (gb + GOFF_WV);

    // balanced virtual-group tile range
    const int V  = gridDim.x * 4;
    const int v  = blockIdx.x * 4 + grp;
    int t0 = (int)(((long long)BT * v) / V);
    int t1 = (int)(((long long)BT * (v + 1)) / V);
    int nt = t1 - t0;
    if (nt > MAXT) nt = MAXT;

    // ---- staging: Wk (block-wide), ws/bs; per-group qt, zeros ----
    #pragma unroll 1
    for (int j = tid; j < DOUT * 16; j += TPB) {
        int row = j >> 4, c4 = (j & 15) * 4;
        float4 w = __ldg((const float4*)(Wk + row * DK + c4));
        uint2 hh = make_uint2(f2h2(w.x, w.y), f2h2(w.z, w.w));
        *(uint2*)(s_wkh + row * STRH + c4) = hh;
    }
    if (tid < DK) s_ws[tid] = Ws[tid];
    if (tid == 0) s_bs[0] = bs[0];
    if (wtid < 16) {   // zero kv row 127 in this group's buffer
        uint2 z = make_uint2(0u, 0u);
        *(uint2*)(s_kvh + 127 * STRH + wtid * 4) = z;
    }
    for (int j = wtid; j < 16 * STRW / 2; j += GTH)
        ((uint32_t*)s_w16)[j] = 0u;
    for (int idx = wtid; idx < nt * DK; idx += GTH) {
        int t = idx >> 6, k = idx & 63;
        s_qt[t * DK + k] = q_x[(size_t)(t0 + t) * DK + k];
    }
    __syncthreads();

    // ---- per-group qb prologue; thread covers o = wtid, wtid+128 ----
    #pragma unroll 1
    for (int rep = 0; rep < 2; ++rep) {
        const int o = wtid + rep * 128;
        float4 wq[16];
        const float4* wq4 = (const float4*)(Wq + o * DK);
        #pragma unroll
        for (int i = 0; i < 16; i++) wq[i] = __ldg(wq4 + i);
        const float bb = __ldg(bias + (o & (DK - 1)));
        #pragma unroll 1
        for (int t = 0; t < nt; ++t) {
            const float* qq = s_qt + t * DK;
            float a0 = 0.f, a1 = 0.f, a2 = 0.f, a3 = 0.f;
            #pragma unroll
            for (int i = 0; i < 16; i++) {
                a0 = fmaf(qq[4 * i + 0], wq[i].x, a0);
                a1 = fmaf(qq[4 * i + 1], wq[i].y, a1);
                a2 = fmaf(qq[4 * i + 2], wq[i].z, a2);
                a3 = fmaf(qq[4 * i + 3], wq[i].w, a3);
            }
            s_qba[t * DOUT + o] = (a0 + a1) + (a2 + a3) + bb;
        }
    }

    // ---- convert first tile ----
    if (nt > 0)
        convert_kv(kv_x + (size_t)t0 * (NKEY * DK), s_kvh, wtid);
    __syncthreads();   // all groups: init + first kv ready

    #pragma unroll 1
    for (int it = 0; it < nt; ++it) {
        const int bt = t0 + it;
        const float* qbt = s_qba + it * DOUT;
        const float  bsv = s_bs[0];
        const int head = wrp;
        const __half* wkp = s_wkh + (head * 64) * STRH;

        // ---- score GEMM + f16x2-tanh epilogue; scores in regs ----
        float sc[16];          // i = nh*4+mb*2+p -> n = nh*32+mb*16+p*8+g
        #pragma unroll 1
        for (int nh = 0; nh < 4; ++nh) {
            const __half* kvp = s_kvh + (nh * 32) * STRH;

            float acc[2][8][4];
            #pragma unroll
            for (int mb = 0; mb < 2; ++mb)
                #pragma unroll
                for (int nb = 0; nb < 8; ++nb)
                    #pragma unroll
                    for (int c = 0; c < 4; ++c) acc[mb][nb][c] = 0.f;

            #pragma unroll
            for (int kc = 0; kc < 4; ++kc) {
                const int ho = kc * 16 + 4 * tg;   // permuted k slots
                uint2 u[2], w2[2];
                #pragma unroll
                for (int mb = 0; mb < 2; ++mb) {
                    const __half* ar = kvp + (mb * 16 + g) * STRH + ho;
                    u[mb]  = *(const uint2*)ar;
                    w2[mb] = *(const uint2*)(ar + 8 * STRH);
                }
                #pragma unroll
                for (int nb = 0; nb < 8; ++nb) {
                    uint2 w = *(const uint2*)(wkp + (nb * 8 + g) * STRH + ho);
                    #pragma unroll
                    for (int mb = 0; mb < 2; ++mb)
                        mma16(acc[mb][nb][0], acc[mb][nb][1],
                              acc[mb][nb][2], acc[mb][nb][3],
                              u[mb].x, w2[mb].x, u[mb].y, w2[mb].y,
                              w.x, w.y);
                }
            }

            float part[2][2];
            part[0][0] = part[0][1] = part[1][0] = part[1][1] = 0.f;
            #pragma unroll
            for (int nb = 0; nb < 8; ++nb) {
                #pragma unroll
                for (int cc = 0; cc < 2; ++cc) {
                    const int k = nb * 8 + tg * 2 + cc;
                    const float wsk = s_ws[k];
                    const float qbo = qbt[head * 64 + k];
                    #pragma unroll
                    for (int mb = 0; mb < 2; ++mb) {
                        uint32_t pk = f2h2(acc[mb][nb][cc] + qbo,
                                           acc[mb][nb][2 + cc] + qbo);
                        uint32_t th = tanh_h2(pk);
                        float2 tf = __half22float2(*(__half2*)&th);
                        part[mb][0] = fmaf(wsk, tf.x, part[mb][0]);
                        part[mb][1] = fmaf(wsk, tf.y, part[mb][1]);
                    }
                }
            }
            #pragma unroll
            for (int m = 1; m <= 2; m <<= 1) {
                #pragma unroll
                for (int mb = 0; mb < 2; ++mb) {
                    part[mb][0] += __shfl_xor_sync(0xffffffffu, part[mb][0], m);
                    part[mb][1] += __shfl_xor_sync(0xffffffffu, part[mb][1], m);
                }
            }
            sc[nh * 4 + 0] = part[0][0] + bsv;
            sc[nh * 4 + 1] = part[0][1] + bsv;
            sc[nh * 4 + 2] = part[1][0] + bsv;
            sc[nh * 4 + 3] = part[1][1] + bsv;
        }
        if (g == 7) sc[15] = -1e30f;   // mask n = 127

        // ---- in-register softmax over 128 scores ----
        float mx = -1e30f;
        #pragma unroll
        for (int i = 0; i < 16; ++i) mx = fmaxf(mx, sc[i]);
        #pragma unroll
        for (int off = 4; off <= 16; off <<= 1)
            mx = fmaxf(mx, __shfl_xor_sync(0xffffffffu, mx, off));
        float sum = 0.f;
        #pragma unroll
        for (int i = 0; i < 16; ++i) {
            sc[i] = __expf(sc[i] - mx);
            sum += sc[i];
        }
        #pragma unroll
        for (int off = 4; off <= 16; off <<= 1)
            sum += __shfl_xor_sync(0xffffffffu, sum, off);
        const float inv = 1.f / sum;
        if (tg == 0) {
            #pragma unroll
            for (int i = 0; i < 16; ++i) {
                const int n = (i >> 2) * 32 + ((i >> 1) & 1) * 16 +
                              (i & 1) * 8 + g;
                s_w16[head * STRW + n] = __float2half(sc[i] * inv);
            }
        }
        GBAR(grp + 1);         // all 4 w rows ready

        // ---- P·V via tensor cores: warp owns 16 cols ----
        {
            const int c0 = wrp * 16;
            float pv[2][4];
            #pragma unroll
            for (int cc = 0; cc < 2; ++cc)
                #pragma unroll
                for (int c = 0; c < 4; ++c) pv[cc][c] = 0.f;

            #pragma unroll
            for (int kc = 0; kc < 8; ++kc) {
                const int k0 = kc * 16;
                uint32_t a0 = *(const uint32_t*)(s_w16 + g * STRW + k0 + 2 * tg);
                uint32_t a1 = *(const uint32_t*)(s_w16 + (g + 8) * STRW + k0 + 2 * tg);
                uint32_t a2 = *(const uint32_t*)(s_w16 + g * STRW + k0 + 8 + 2 * tg);
                uint32_t a3 = *(const uint32_t*)(s_w16 + (g + 8) * STRW + k0 + 8 + 2 * tg);
                #pragma unroll
                for (int cc = 0; cc < 2; ++cc) {
                    uint32_t baddr = (uint32_t)__cvta_generic_to_shared(
                        s_kvh + (k0 + (lane & 15)) * STRH + c0 + cc * 8);
                    uint32_t b0, b1;
                    ldmx2t(b0, b1, baddr);
                    mma16(pv[cc][0], pv[cc][1], pv[cc][2], pv[cc][3],
                          a0, a1, a2, a3, b0, b1);
                }
            }
            if (g < NH) {
                #pragma unroll
                for (int cc = 0; cc < 2; ++cc) {
                    s_wv[g * 64 + c0 + cc * 8 + 2 * tg]     = pv[cc][0];
                    s_wv[g * 64 + c0 + cc * 8 + 2 * tg + 1] = pv[cc][1];
                }
            }
        }
        GBAR(grp + 1);         // wv ready; kv dead

        // ---- convert next tile (LDG-shadowed) + out-projection ----
        if (it + 1 < nt)
            convert_kv(kv_x + (size_t)(bt + 1) * (NKEY * DK), s_kvh, wtid);

        #pragma unroll 1
        for (int rep = 0; rep < 2; ++rep) {
            const int o = wtid + rep * 128;
            const float* wvh = s_wv + (o >> 6) * 64;
            const float4* wv4 = (const float4*)(Wv + o * DK);
            float a0 = 0.f, a1 = 0.f, a2 = 0.f, a3 = 0.f;
            #pragma unroll
            for (int i = 0; i < 16; i++) {
                float4 w = __ldg(wv4 + i);
                a0 = fmaf(wvh[4 * i + 0], w.x, a0);
                a1 = fmaf(wvh[4 * i + 1], w.y, a1);
                a2 = fmaf(wvh[4 * i + 2], w.z, a2);
                a3 = fmaf(wvh[4 * i + 3], w.w, a3);
            }
            out[(size_t)bt * DOUT + o] = (a0 + a1) + (a2 + a3);
        }
        GBAR(grp + 1);         // kv(next) ready / wv consumed
    }
}

extern "C" void kernel_launch(void* const* d_in, const int* in_sizes, int n_in,
                              void* d_out, int out_size) {
    (void)n_in; (void)out_size;
    const float* q_x  = (const float*)d_in[0];
    const float* kv_x = (const float*)d_in[1];
    const float* Wk   = (const float*)d_in[2];
    const float* Wq   = (const float*)d_in[3];
    const float* Wv   = (const float*)d_in[4];
    const float* bias = (const float*)d_in[5];
    const float* Ws   = (const float*)d_in[6];
    const float* bs   = (const float*)d_in[7];
    float* out = (float*)d_out;

    const int BT = in_sizes[0] / DK;
    int grid = 152;
    // keep per-group tile count within MAXT
    while (BT > grid * 4 * MAXT) grid += 152;

    cudaFuncSetAttribute(raamh_kernel,
                         cudaFuncAttributeMaxDynamicSharedMemorySize,
                         SMEM_BYTES);
    raamh_kernel<<<grid, TPB, SMEM_BYTES>>>(q_x, kv_x, Wk, Wq, Wv,
                                            bias, Ws, bs, out, BT);
}

// round 17
// speedup vs baseline: 1.3202x; 1.2303x over previous
#include <cuda_runtime.h>
#include <cuda_fp16.h>
#include <cstdint>
#include <cstddef>

#define TPB   512
#define GTH   128   // threads per group
#define NKEY  127
#define NH    4
#define DK    64
#define DOUT  256
#define STRH  80    // fp16 kv/wk row stride in halves (160B)
#define STRV  72    // fp16 Wv row stride in halves (144B)
#define STRW  136   // fp16 w row stride in halves
#define MAXT  4

// shared region
static constexpr int OFF_WK  = 0;                        // 256*80*2 = 40960
static constexpr int OFF_WV16 = OFF_WK + 256 * STRH * 2; // 256*72*2 = 36864
static constexpr int OFF_WS  = OFF_WV16 + 256 * STRV * 2;
static constexpr int OFF_BS  = OFF_WS + DK * 4;
static constexpr int OFF_GRP = OFF_BS + 16;
// per-group region
static constexpr int GOFF_KV  = 0;                           // 20480
static constexpr int GOFF_QBA = GOFF_KV + 128 * STRH * 2;    // MAXT*1024
static constexpr int GOFF_QT  = GOFF_QBA + MAXT * DOUT * 4;  // MAXT*256
static constexpr int GOFF_W16 = GOFF_QT + MAXT * DK * 4;     // 4352
static constexpr int GOFF_WV  = GOFF_W16 + 16 * STRW * 2;    // 1024
static constexpr int GRP_SZ   = GOFF_WV + DOUT * 4;
static constexpr int SMEM_BYTES = OFF_GRP + 4 * GRP_SZ;      // ~218 KB

__device__ __forceinline__ uint32_t f2h2(float a, float b) {
    __half2 h = __floats2half2_rn(a, b);
    return *(uint32_t*)&h;
}
__device__ __forceinline__ uint32_t tanh_h2(uint32_t x) {
    uint32_t y;
    asm("tanh.approx.f16x2 %0, %1;" : "=r"(y) : "r"(x));
    return y;
}
#define GBAR(id)                                                              \
    asm volatile("bar.sync %0, %1;" :: "r"(id), "r"(GTH) : "memory")

// m16n8k16 fp16 MMA, row(A) x col(B), fp32 accumulate (arch-neutral PTX)
__device__ __forceinline__ void mma16(float& d0, float& d1, float& d2,
                                      float& d3, uint32_t a0, uint32_t a1,
                                      uint32_t a2, uint32_t a3,
                                      uint32_t b0, uint32_t b1) {
    asm volatile(
        "mma.sync.aligned.m16n8k16.row.col.f32.f16.f16.f32 "
        "{%0,%1,%2,%3}, {%4,%5,%6,%7}, {%8,%9}, {%0,%1,%2,%3};"
        : "+f"(d0), "+f"(d1), "+f"(d2), "+f"(d3)
        : "r"(a0), "r"(a1), "r"(a2), "r"(a3), "r"(b0), "r"(b1));
}
__device__ __forceinline__ void ldmx2t(uint32_t& r0, uint32_t& r1,
                                       uint32_t saddr) {
    asm volatile(
        "ldmatrix.sync.aligned.m8n8.x2.trans.shared.b16 {%0,%1}, [%2];"
        : "=r"(r0), "=r"(r1) : "r"(saddr));
}

// direct gmem->fp16 smem convert of one kv tile (group-local, 128 threads)
__device__ __forceinline__ void convert_kv(const float* __restrict__ gsrc,
                                           __half* s_kvh, int wtid) {
    #pragma unroll 4
    for (int j = wtid; j < NKEY * 16; j += GTH) {
        int row = j >> 4, c4 = (j & 15) * 4;
        float4 v = __ldg((const float4*)(gsrc + j * 4));
        uint2 hh = make_uint2(f2h2(v.x, v.y), f2h2(v.z, v.w));
        *(uint2*)(s_kvh + row * STRH + c4) = hh;
    }
}

__global__ void __launch_bounds__(TPB)
raamh_kernel(const float* __restrict__ q_x, const float* __restrict__ kv_x,
             const float* __restrict__ Wk,  const float* __restrict__ Wq,
             const float* __restrict__ Wv,  const float* __restrict__ bias,
             const float* __restrict__ Ws,  const float* __restrict__ bs,
             float* __restrict__ out, int BT)
{
    extern __shared__ char smem[];
    __half* s_wkh  = (__half*)(smem + OFF_WK);
    __half* s_wvh16= (__half*)(smem + OFF_WV16);
    float*  s_ws   = (float*) (smem + OFF_WS);
    float*  s_bs   = (float*) (smem + OFF_BS);

    const int tid  = threadIdx.x;
    const int grp  = tid >> 7;       // group 0..3
    const int wtid = tid & 127;      // thread within group
    const int lane = tid & 31;
    const int wrp  = wtid >> 5;      // head within group
    const int g    = lane >> 2;
    const int tg   = lane & 3;

    char*   gb    = smem + OFF_GRP + grp * GRP_SZ;
    __half* s_kvh = (__half*)(gb + GOFF_KV);
    float*  s_qba = (float*) (gb + GOFF_QBA);
    float*  s_qt  = (float*) (gb + GOFF_QT);
    __half* s_w16 = (__half*)(gb + GOFF_W16);
    float*  s_wv  = (float*) (gb + GOFF_WV);

    // balanced virtual-group tile range
    const int V  = gridDim.x * 4;
    const int v  = blockIdx.x * 4 + grp;
    int t0 = (int)(((long long)BT * v) / V);
    int t1 = (int)(((long long)BT * (v + 1)) / V);
    int nt = t1 - t0;
    if (nt > MAXT) nt = MAXT;

    // ---- staging: Wk + Wv (block-wide, fp16), ws/bs; per-group qt, zeros ----
    #pragma unroll 1
    for (int j = tid; j < DOUT * 16; j += TPB) {
        int row = j >> 4, c4 = (j & 15) * 4;
        float4 w = __ldg((const float4*)(Wk + row * DK + c4));
        uint2 hh = make_uint2(f2h2(w.x, w.y), f2h2(w.z, w.w));
        *(uint2*)(s_wkh + row * STRH + c4) = hh;
    }
    #pragma unroll 1
    for (int j = tid; j < DOUT * 16; j += TPB) {
        int row = j >> 4, c4 = (j & 15) * 4;
        float4 w = __ldg((const float4*)(Wv + row * DK + c4));
        uint2 hh = make_uint2(f2h2(w.x, w.y), f2h2(w.z, w.w));
        *(uint2*)(s_wvh16 + row * STRV + c4) = hh;
    }
    if (tid < DK) s_ws[tid] = Ws[tid];
    if (tid == 0) s_bs[0] = bs[0];
    if (wtid < 16) {   // zero kv row 127 in this group's buffer
        uint2 z = make_uint2(0u, 0u);
        *(uint2*)(s_kvh + 127 * STRH + wtid * 4) = z;
    }
    for (int j = wtid; j < 16 * STRW / 2; j += GTH)
        ((uint32_t*)s_w16)[j] = 0u;
    for (int idx = wtid; idx < nt * DK; idx += GTH) {
        int t = idx >> 6, k = idx & 63;
        s_qt[t * DK + k] = q_x[(size_t)(t0 + t) * DK + k];
    }
    __syncthreads();

    // ---- per-group qb prologue; thread covers o = wtid, wtid+128 ----
    #pragma unroll 1
    for (int rep = 0; rep < 2; ++rep) {
        const int o = wtid + rep * 128;
        float4 wq[16];
        const float4* wq4 = (const float4*)(Wq + o * DK);
        #pragma unroll
        for (int i = 0; i < 16; i++) wq[i] = __ldg(wq4 + i);
        const float bb = __ldg(bias + (o & (DK - 1)));
        #pragma unroll 1
        for (int t = 0; t < nt; ++t) {
            const float* qq = s_qt + t * DK;
            float a0 = 0.f, a1 = 0.f, a2 = 0.f, a3 = 0.f;
            #pragma unroll
            for (int i = 0; i < 16; i++) {
                a0 = fmaf(qq[4 * i + 0], wq[i].x, a0);
                a1 = fmaf(qq[4 * i + 1], wq[i].y, a1);
                a2 = fmaf(qq[4 * i + 2], wq[i].z, a2);
                a3 = fmaf(qq[4 * i + 3], wq[i].w, a3);
            }
            s_qba[t * DOUT + o] = (a0 + a1) + (a2 + a3) + bb;
        }
    }

    // ---- convert first tile ----
    if (nt > 0)
        convert_kv(kv_x + (size_t)t0 * (NKEY * DK), s_kvh, wtid);
    __syncthreads();   // all groups: init + first kv ready

    #pragma unroll 1
    for (int it = 0; it < nt; ++it) {
        const int bt = t0 + it;
        const float* qbt = s_qba + it * DOUT;
        const float  bsv = s_bs[0];
        const int head = wrp;
        const __half* wkp = s_wkh + (head * 64) * STRH;

        // ---- score GEMM + f16x2-tanh epilogue; scores in regs ----
        float sc[16];          // i = nh*4+mb*2+p -> n = nh*32+mb*16+p*8+g
        #pragma unroll 1
        for (int nh = 0; nh < 4; ++nh) {
            const __half* kvp = s_kvh + (nh * 32) * STRH;

            float acc[2][8][4];
            #pragma unroll
            for (int mb = 0; mb < 2; ++mb)
                #pragma unroll
                for (int nb = 0; nb < 8; ++nb)
                    #pragma unroll
                    for (int c = 0; c < 4; ++c) acc[mb][nb][c] = 0.f;

            #pragma unroll
            for (int kc = 0; kc < 4; ++kc) {
                const int ho = kc * 16 + 4 * tg;   // permuted k slots
                uint2 u[2], w2[2];
                #pragma unroll
                for (int mb = 0; mb < 2; ++mb) {
                    const __half* ar = kvp + (mb * 16 + g) * STRH + ho;
                    u[mb]  = *(const uint2*)ar;
                    w2[mb] = *(const uint2*)(ar + 8 * STRH);
                }
                #pragma unroll
                for (int nb = 0; nb < 8; ++nb) {
                    uint2 w = *(const uint2*)(wkp + (nb * 8 + g) * STRH + ho);
                    #pragma unroll
                    for (int mb = 0; mb < 2; ++mb)
                        mma16(acc[mb][nb][0], acc[mb][nb][1],
                              acc[mb][nb][2], acc[mb][nb][3],
                              u[mb].x, w2[mb].x, u[mb].y, w2[mb].y,
                              w.x, w.y);
                }
            }

            float part[2][2];
            part[0][0] = part[0][1] = part[1][0] = part[1][1] = 0.f;
            #pragma unroll
            for (int nb = 0; nb < 8; ++nb) {
                #pragma unroll
                for (int cc = 0; cc < 2; ++cc) {
                    const int k = nb * 8 + tg * 2 + cc;
                    const float wsk = s_ws[k];
                    const float qbo = qbt[head * 64 + k];
                    #pragma unroll
                    for (int mb = 0; mb < 2; ++mb) {
                        uint32_t pk = f2h2(acc[mb][nb][cc] + qbo,
                                           acc[mb][nb][2 + cc] + qbo);
                        uint32_t th = tanh_h2(pk);
                        float2 tf = __half22float2(*(__half2*)&th);
                        part[mb][0] = fmaf(wsk, tf.x, part[mb][0]);
                        part[mb][1] = fmaf(wsk, tf.y, part[mb][1]);
                    }
                }
            }
            #pragma unroll
            for (int m = 1; m <= 2; m <<= 1) {
                #pragma unroll
                for (int mb = 0; mb < 2; ++mb) {
                    part[mb][0] += __shfl_xor_sync(0xffffffffu, part[mb][0], m);
                    part[mb][1] += __shfl_xor_sync(0xffffffffu, part[mb][1], m);
                }
            }
            sc[nh * 4 + 0] = part[0][0] + bsv;
            sc[nh * 4 + 1] = part[0][1] + bsv;
            sc[nh * 4 + 2] = part[1][0] + bsv;
            sc[nh * 4 + 3] = part[1][1] + bsv;
        }
        if (g == 7) sc[15] = -1e30f;   // mask n = 127

        // ---- in-register softmax over 128 scores ----
        float mx = -1e30f;
        #pragma unroll
        for (int i = 0; i < 16; ++i) mx = fmaxf(mx, sc[i]);
        #pragma unroll
        for (int off = 4; off <= 16; off <<= 1)
            mx = fmaxf(mx, __shfl_xor_sync(0xffffffffu, mx, off));
        float sum = 0.f;
        #pragma unroll
        for (int i = 0; i < 16; ++i) {
            sc[i] = __expf(sc[i] - mx);
            sum += sc[i];
        }
        #pragma unroll
        for (int off = 4; off <= 16; off <<= 1)
            sum += __shfl_xor_sync(0xffffffffu, sum, off);
        const float inv = 1.f / sum;
        if (tg == 0) {
            #pragma unroll
            for (int i = 0; i < 16; ++i) {
                const int n = (i >> 2) * 32 + ((i >> 1) & 1) * 16 +
                              (i & 1) * 8 + g;
                s_w16[head * STRW + n] = __float2half(sc[i] * inv);
            }
        }
        GBAR(grp + 1);         // all 4 w rows ready

        // ---- P·V via tensor cores: warp owns 16 cols ----
        {
            const int c0 = wrp * 16;
            float pv[2][4];
            #pragma unroll
            for (int cc = 0; cc < 2; ++cc)
                #pragma unroll
                for (int c = 0; c < 4; ++c) pv[cc][c] = 0.f;

            #pragma unroll
            for (int kc = 0; kc < 8; ++kc) {
                const int k0 = kc * 16;
                uint32_t a0 = *(const uint32_t*)(s_w16 + g * STRW + k0 + 2 * tg);
                uint32_t a1 = *(const uint32_t*)(s_w16 + (g + 8) * STRW + k0 + 2 * tg);
                uint32_t a2 = *(const uint32_t*)(s_w16 + g * STRW + k0 + 8 + 2 * tg);
                uint32_t a3 = *(const uint32_t*)(s_w16 + (g + 8) * STRW + k0 + 8 + 2 * tg);
                #pragma unroll
                for (int cc = 0; cc < 2; ++cc) {
                    uint32_t baddr = (uint32_t)__cvta_generic_to_shared(
                        s_kvh + (k0 + (lane & 15)) * STRH + c0 + cc * 8);
                    uint32_t b0, b1;
                    ldmx2t(b0, b1, baddr);
                    mma16(pv[cc][0], pv[cc][1], pv[cc][2], pv[cc][3],
                          a0, a1, a2, a3, b0, b1);
                }
            }
            if (g < NH) {
                #pragma unroll
                for (int cc = 0; cc < 2; ++cc) {
                    s_wv[g * 64 + c0 + cc * 8 + 2 * tg]     = pv[cc][0];
                    s_wv[g * 64 + c0 + cc * 8 + 2 * tg + 1] = pv[cc][1];
                }
            }
        }
        GBAR(grp + 1);         // wv ready; kv dead

        // ---- convert next tile (LDG-shadowed) + out-projection ----
        if (it + 1 < nt)
            convert_kv(kv_x + (size_t)(bt + 1) * (NKEY * DK), s_kvh, wtid);

        #pragma unroll 1
        for (int rep = 0; rep < 2; ++rep) {
            const int o = wtid + rep * 128;
            const float*  wvh = s_wv + (o >> 6) * 64;   // broadcast reads
            const __half* wr  = s_wvh16 + (size_t)o * STRV;
            float a0 = 0.f, a1 = 0.f, a2 = 0.f, a3 = 0.f;
            #pragma unroll
            for (int i = 0; i < 8; i++) {
                uint4 h8 = *(const uint4*)(wr + i * 8);
                float2 f0 = __half22float2(*(__half2*)&h8.x);
                float2 f1 = __half22float2(*(__half2*)&h8.y);
                float2 f2 = __half22float2(*(__half2*)&h8.z);
                float2 f3 = __half22float2(*(__half2*)&h8.w);
                const float* vv = wvh + i * 8;
                a0 = fmaf(vv[0], f0.x, a0);
                a1 = fmaf(vv[1], f0.y, a1);
                a2 = fmaf(vv[2], f1.x, a2);
                a3 = fmaf(vv[3], f1.y, a3);
                a0 = fmaf(vv[4], f2.x, a0);
                a1 = fmaf(vv[5], f2.y, a1);
                a2 = fmaf(vv[6], f3.x, a2);
                a3 = fmaf(vv[7], f3.y, a3);
            }
            out[(size_t)bt * DOUT + o] = (a0 + a1) + (a2 + a3);
        }
        GBAR(grp + 1);         // kv(next) ready / wv consumed
    }
}

extern "C" void kernel_launch(void* const* d_in, const int* in_sizes, int n_in,
                              void* d_out, int out_size) {
    (void)n_in; (void)out_size;
    const float* q_x  = (const float*)d_in[0];
    const float* kv_x = (const float*)d_in[1];
    const float* Wk   = (const float*)d_in[2];
    const float* Wq   = (const float*)d_in[3];
    const float* Wv   = (const float*)d_in[4];
    const float* bias = (const float*)d_in[5];
    const float* Ws   = (const float*)d_in[6];
    const float* bs   = (const float*)d_in[7];
    float* out = (float*)d_out;

    const int BT = in_sizes[0] / DK;
    int grid = 152;
    while (BT > grid * 4 * MAXT) grid += 152;

    cudaFuncSetAttribute(raamh_kernel,
                         cudaFuncAttributeMaxDynamicSharedMemorySize,
                         SMEM_BYTES);
    raamh_kernel<<<grid, TPB, SMEM_BYTES>>>(q_x, kv_x, Wk, Wq, Wv,
                                            bias, Ws, bs, out, BT);
}